// round 4
// baseline (speedup 1.0000x reference)
#include <cuda_runtime.h>
#include <cuda_bf16.h>
#include <math_constants.h>

#define N_NODES 50000
#define N_EDGES 800000
#define NODE_DIM 64
#define EDGE_DIM 32
#define IN_DIM   160
#define OUT_F    64
#define WROW     164              // padded weight row (words)

#define SCAN_BLK 512
#define SCAN_NBLK ((N_NODES + SCAN_BLK - 1) / SCAN_BLK)   // 98

// ---------------- static scratch ----------------
__device__ float g_ps[N_NODES];
__device__ float g_pd[N_NODES];
__device__ float g_r [N_NODES];
__device__ float g_ssrc[N_NODES];
__device__ float g_sdst[N_NODES];
__device__ int   g_cnt[N_NODES];
__device__ int   g_off[N_NODES + 1];
__device__ int   g_cur[N_NODES];
__device__ int   g_aux[SCAN_NBLK];

__device__ float g_ee [N_EDGES];
__device__ float g_et [N_EDGES];
__device__ int   g_pos[N_EDGES];
__device__ int   g_srcs[N_EDGES];
__device__ int   g_eids[N_EDGES];
__device__ float2 g_w12[N_EDGES];

// ---------------- packed f32x2 helpers ----------------
__device__ __forceinline__ unsigned long long fma2(unsigned long long a,
                                                   unsigned long long b,
                                                   unsigned long long c) {
    unsigned long long d;
    asm("fma.rn.f32x2 %0, %1, %2, %3;" : "=l"(d) : "l"(a), "l"(b), "l"(c));
    return d;
}
__device__ __forceinline__ unsigned long long pack2(float x, float y) {
    unsigned long long r;
    asm("mov.b64 %0, {%1, %2};" : "=l"(r) : "f"(x), "f"(y));
    return r;
}
__device__ __forceinline__ float2 unpack2(unsigned long long v) {
    float2 r;
    asm("mov.b64 {%0, %1}, %2;" : "=f"(r.x), "=f"(r.y) : "l"(v));
    return r;
}

// ---------------- K0 ----------------
__global__ void k_init() {
    int i = blockIdx.x * blockDim.x + threadIdx.x;
    if (i < N_NODES) { g_ssrc[i] = 0.f; g_sdst[i] = 0.f; g_cnt[i] = 0; }
}

// ---------------- K1: per-node dots ----------------
__global__ void k_node_pre(const float* __restrict__ h,
                           const float* __restrict__ wg,
                           const float* __restrict__ wa) {
    int node = blockIdx.x * (blockDim.x >> 5) + (threadIdx.x >> 5);
    int lane = threadIdx.x & 31;
    if (node >= N_NODES) return;
    const float* hp = h + (size_t)node * NODE_DIM;
    float v0 = hp[lane];
    float v1 = hp[lane + 32];
    float ps = v0 * wg[32 + lane]  + v1 * wg[64 + lane];
    float pd = v0 * wg[96 + lane]  + v1 * wg[128 + lane];
    float r  = v0 * wa[lane]       + v1 * wa[32 + lane];
    #pragma unroll
    for (int o = 16; o; o >>= 1) {
        ps += __shfl_xor_sync(0xffffffffu, ps, o);
        pd += __shfl_xor_sync(0xffffffffu, pd, o);
        r  += __shfl_xor_sync(0xffffffffu, r,  o);
    }
    if (lane == 0) { g_ps[node] = ps; g_pd[node] = pd; g_r[node] = r; }
}

// ---------------- K2: histogram ----------------
__global__ void k_hist(const int* __restrict__ dst) {
    int e = blockIdx.x * blockDim.x + threadIdx.x;
    if (e < N_EDGES) atomicAdd(&g_cnt[dst[e]], 1);
}

// ---------------- K3: scan ----------------
__global__ void k_scan1() {
    __shared__ int sh[SCAN_BLK];
    int tid = threadIdx.x;
    int i = blockIdx.x * SCAN_BLK + tid;
    int v = (i < N_NODES) ? g_cnt[i] : 0;
    sh[tid] = v;
    __syncthreads();
    #pragma unroll
    for (int off = 1; off < SCAN_BLK; off <<= 1) {
        int t = (tid >= off) ? sh[tid - off] : 0;
        __syncthreads();
        sh[tid] += t;
        __syncthreads();
    }
    if (i < N_NODES) g_off[i] = sh[tid] - v;
    if (tid == SCAN_BLK - 1) g_aux[blockIdx.x] = sh[tid];
}
__global__ void k_scan2() {
    if (threadIdx.x == 0) {
        int run = 0;
        for (int b = 0; b < SCAN_NBLK; b++) { int t = g_aux[b]; g_aux[b] = run; run += t; }
    }
}
__global__ void k_scan3() {
    int i = blockIdx.x * SCAN_BLK + threadIdx.x;
    if (i < N_NODES) {
        int o = g_off[i] + g_aux[blockIdx.x];
        g_off[i] = o;
        g_cur[i] = o;
    }
    if (i == 0) g_off[N_NODES] = N_EDGES;
}

// ---------------- K4: scores + CSR fill (8 lanes/edge) ----------------
__global__ void k_fill(const float* __restrict__ ef,
                       const int* __restrict__ src,
                       const int* __restrict__ dst,
                       const float* __restrict__ wg,
                       const float* __restrict__ wa) {
    int gid = blockIdx.x * blockDim.x + threadIdx.x;
    int e = gid >> 3;
    int k = gid & 7;
    if (e >= N_EDGES) return;
    float4 v  = ((const float4*)ef)[(size_t)e * 8 + k];
    float4 w1 = ((const float4*)wg)[k];
    float4 w2 = ((const float4*)wa)[16 + k];
    float qe = v.x * w1.x + v.y * w1.y + v.z * w1.z + v.w * w1.w;
    float te = v.x * w2.x + v.y * w2.y + v.z * w2.z + v.w * w2.w;
    #pragma unroll
    for (int o = 4; o; o >>= 1) {
        qe += __shfl_xor_sync(0xffffffffu, qe, o);
        te += __shfl_xor_sync(0xffffffffu, te, o);
    }
    if (k == 0) {
        int s = src[e];
        int d = dst[e];
        float a  = qe + g_ps[s] + g_pd[d];
        float ee = __expf(a);              // scores O(1): max-free softmax
        g_ee[e] = ee;
        g_et[e] = te;
        atomicAdd(&g_ssrc[s], ee);
        int p = atomicAdd(&g_cur[d], 1);
        g_pos[e]  = p;
        g_srcs[p] = s;
        g_eids[p] = e;
    }
}

// ---------------- K5: final edge weights into sorted slots ----------------
__global__ void k_edge2(const int* __restrict__ src,
                        const int* __restrict__ dst) {
    int e = blockIdx.x * blockDim.x + threadIdx.x;
    if (e >= N_EDGES) return;
    int s = src[e];
    float gamma = g_ee[e] / g_ssrc[s];
    float sc = g_r[s] + gamma * g_et[e];
    float w  = __expf(sc);
    g_w12[g_pos[e]] = make_float2(w, w * gamma);
    atomicAdd(&g_sdst[dst[e]], w);
}

// ---------------- K6: gather (4 nodes/warp) + amortized GEMV ----------------
// dynamic smem layout:
//   s_wT   : OUT_F * WROW floats        (41.98 KB) transposed weights
//   s_hc   : 8 warps * 4 nodes * 160 f  (20 KB)
//   s_meta : 8 warps * 32 float4        (4 KB)
__global__ void __launch_bounds__(256) k_gather_out(
        const float* __restrict__ h,
        const float* __restrict__ ef,
        const float* __restrict__ wlin,
        float* __restrict__ out) {
    extern __shared__ __align__(16) float smem[];
    float*  s_wT   = smem;                                  // [64][WROW]
    float*  s_hc   = smem + OUT_F * WROW;                   // [8][4][160]
    float4* s_meta = (float4*)(s_hc + 8 * 4 * IN_DIM);      // [8][32]

    int tid  = threadIdx.x;
    int warp = tid >> 5;
    int lane = tid & 31;

    for (int i = tid; i < IN_DIM * OUT_F; i += blockDim.x) {
        int k = i >> 6, c = i & 63;
        s_wT[c * WROW + k] = wlin[i];
    }
    __syncthreads();

    const unsigned long long* h64 = (const unsigned long long*)h;
    float*  hcW = s_hc + warp * (4 * IN_DIM);
    float4* mW  = s_meta + warp * 32;

    int gwarp  = blockIdx.x * 8 + warp;
    int nwarps = gridDim.x * 8;

    for (int g0 = gwarp * 4; g0 < N_NODES; g0 += nwarps * 4) {
        // ---- phase 1: gather 4 nodes into s_hc ----
        #pragma unroll
        for (int nn = 0; nn < 4; nn++) {
            int node = g0 + nn;
            if (node >= N_NODES) break;
            int beg = g_off[node];
            int end = g_off[node + 1];
            float inv = (end > beg) ? 1.0f / g_sdst[node] : 0.0f;

            unsigned long long accH = 0;
            float accE = 0.0f;

            for (int base = beg; base < end; base += 32) {
                int i = base + lane;
                if (i < end) {
                    float2 w = g_w12[i];
                    mW[lane] = make_float4(w.x * inv, w.y * inv,
                                           __int_as_float(g_srcs[i]),
                                           __int_as_float(g_eids[i]));
                }
                __syncwarp();
                int cnt = min(32, end - base);
                #pragma unroll 4
                for (int j = 0; j < cnt; j++) {
                    float4 m = mW[j];                          // broadcast LDS.128
                    int s  = __float_as_int(m.z);
                    int ej = __float_as_int(m.w);
                    unsigned long long h2 = __ldg(&h64[(size_t)s * 32 + lane]);
                    float ev = __ldg(&ef[(size_t)ej * EDGE_DIM + lane]);
                    accH = fma2(pack2(m.x, m.x), h2, accH);
                    accE = fmaf(m.y, ev, accE);
                }
                __syncwarp();
            }

            float2 own = ((const float2*)h)[(size_t)node * 32 + lane];
            float2 aH  = unpack2(accH);
            float* hc = hcW + nn * IN_DIM;
            ((float2*)hc)[lane]        = own;   // 0..63
            ((float2*)(hc + 64))[lane] = aH;    // 64..127
            hc[128 + lane]             = accE;  // 128..159
        }
        __syncwarp();

        // ---- phase 2: 4-node GEMV, weights read once ----
        unsigned long long aA[4][2] = {};   // col lane,   per node (x,y pair halves)
        unsigned long long aB[4][2] = {};   // col lane+32
        const ulonglong2* wA = (const ulonglong2*)&s_wT[lane * WROW];
        const ulonglong2* wB = (const ulonglong2*)&s_wT[(lane + 32) * WROW];
        const ulonglong2* hv0 = (const ulonglong2*)(hcW + 0 * IN_DIM);
        const ulonglong2* hv1 = (const ulonglong2*)(hcW + 1 * IN_DIM);
        const ulonglong2* hv2 = (const ulonglong2*)(hcW + 2 * IN_DIM);
        const ulonglong2* hv3 = (const ulonglong2*)(hcW + 3 * IN_DIM);

        #pragma unroll 4
        for (int q = 0; q < IN_DIM / 4; q++) {    // 40 iters, 4 k each
            ulonglong2 va = wA[q];
            ulonglong2 vb = wB[q];
            ulonglong2 x0 = hv0[q], x1 = hv1[q], x2 = hv2[q], x3 = hv3[q];
            aA[0][0] = fma2(va.x, x0.x, aA[0][0]); aA[0][1] = fma2(va.y, x0.y, aA[0][1]);
            aA[1][0] = fma2(va.x, x1.x, aA[1][0]); aA[1][1] = fma2(va.y, x1.y, aA[1][1]);
            aA[2][0] = fma2(va.x, x2.x, aA[2][0]); aA[2][1] = fma2(va.y, x2.y, aA[2][1]);
            aA[3][0] = fma2(va.x, x3.x, aA[3][0]); aA[3][1] = fma2(va.y, x3.y, aA[3][1]);
            aB[0][0] = fma2(vb.x, x0.x, aB[0][0]); aB[0][1] = fma2(vb.y, x0.y, aB[0][1]);
            aB[1][0] = fma2(vb.x, x1.x, aB[1][0]); aB[1][1] = fma2(vb.y, x1.y, aB[1][1]);
            aB[2][0] = fma2(vb.x, x2.x, aB[2][0]); aB[2][1] = fma2(vb.y, x2.y, aB[2][1]);
            aB[3][0] = fma2(vb.x, x3.x, aB[3][0]); aB[3][1] = fma2(vb.y, x3.y, aB[3][1]);
        }

        #pragma unroll
        for (int nn = 0; nn < 4; nn++) {
            int node = g0 + nn;
            if (node >= N_NODES) break;
            float2 uA0 = unpack2(aA[nn][0]), uA1 = unpack2(aA[nn][1]);
            float2 uB0 = unpack2(aB[nn][0]), uB1 = unpack2(aB[nn][1]);
            float oA = (uA0.x + uA0.y) + (uA1.x + uA1.y);
            float oB = (uB0.x + uB0.y) + (uB1.x + uB1.y);
            out[(size_t)node * OUT_F + lane]      = fmaxf(oA, 0.f);
            out[(size_t)node * OUT_F + 32 + lane] = fmaxf(oB, 0.f);
        }
        __syncwarp();
    }
}

// ---------------- launcher ----------------
extern "C" void kernel_launch(void* const* d_in, const int* in_sizes, int n_in,
                              void* d_out, int out_size) {
    const float* h   = (const float*)d_in[0];
    const float* ef  = (const float*)d_in[1];
    const int*   src = (const int*)  d_in[2];
    const int*   dst = (const int*)  d_in[3];
    const float* wg  = (const float*)d_in[4];
    const float* wa  = (const float*)d_in[5];
    const float* wl  = (const float*)d_in[6];
    float* out = (float*)d_out;

    const int SMEM = (OUT_F * WROW + 8 * 4 * IN_DIM) * 4 + 8 * 32 * 16;  // ~66.5 KB
    cudaFuncSetAttribute(k_gather_out, cudaFuncAttributeMaxDynamicSharedMemorySize, SMEM);

    k_init<<<(N_NODES + 255) / 256, 256>>>();
    k_node_pre<<<(N_NODES + 7) / 8, 256>>>(h, wg, wa);
    k_hist<<<(N_EDGES + 255) / 256, 256>>>(dst);
    k_scan1<<<SCAN_NBLK, SCAN_BLK>>>();
    k_scan2<<<1, 32>>>();
    k_scan3<<<SCAN_NBLK, SCAN_BLK>>>();
    k_fill<<<((size_t)N_EDGES * 8 + 255) / 256, 256>>>(ef, src, dst, wg, wa);
    k_edge2<<<(N_EDGES + 255) / 256, 256>>>(src, dst);
    k_gather_out<<<592, 256, SMEM>>>(h, ef, wl, out);
}

// round 5
// speedup vs baseline: 1.0419x; 1.0419x over previous
#include <cuda_runtime.h>
#include <cuda_bf16.h>
#include <math_constants.h>

#define N_NODES 50000
#define N_EDGES 800000
#define NODE_DIM 64
#define EDGE_DIM 32
#define IN_DIM   160
#define OUT_F    64
#define WROW     164

#define SCAN_BLK 512
#define SCAN_NBLK ((N_NODES + SCAN_BLK - 1) / SCAN_BLK)   // 98

// ---------------- static scratch ----------------
__device__ float g_ps[N_NODES];
__device__ float g_pd[N_NODES];
__device__ float2 g_sr[N_NODES];        // (.x = sum exp(a) per src, .y = h.wa[0:64])
__device__ int   g_cnt[N_NODES];
__device__ int   g_off[N_NODES + 1];
__device__ int   g_cur[N_NODES];
__device__ int   g_aux[SCAN_NBLK];

__device__ int2   g_se [N_EDGES];       // (src, eid), dst-sorted
__device__ float2 g_eet[N_EDGES];       // (exp(a), e_ft.wa[64:96]), dst-sorted

// ---------------- packed f32x2 helpers ----------------
__device__ __forceinline__ unsigned long long fma2(unsigned long long a,
                                                   unsigned long long b,
                                                   unsigned long long c) {
    unsigned long long d;
    asm("fma.rn.f32x2 %0, %1, %2, %3;" : "=l"(d) : "l"(a), "l"(b), "l"(c));
    return d;
}
__device__ __forceinline__ unsigned long long pack2(float x, float y) {
    unsigned long long r;
    asm("mov.b64 %0, {%1, %2};" : "=l"(r) : "f"(x), "f"(y));
    return r;
}
__device__ __forceinline__ float2 unpack2(unsigned long long v) {
    float2 r;
    asm("mov.b64 {%0, %1}, %2;" : "=f"(r.x), "=f"(r.y) : "l"(v));
    return r;
}

// ---------------- K1: per-node dots + init (1 warp / node) ----------------
__global__ void k_node_pre(const float* __restrict__ h,
                           const float* __restrict__ wg,
                           const float* __restrict__ wa) {
    int node = blockIdx.x * (blockDim.x >> 5) + (threadIdx.x >> 5);
    int lane = threadIdx.x & 31;
    if (node >= N_NODES) return;
    const float* hp = h + (size_t)node * NODE_DIM;
    float v0 = hp[lane];
    float v1 = hp[lane + 32];
    float ps = v0 * wg[32 + lane]  + v1 * wg[64 + lane];
    float pd = v0 * wg[96 + lane]  + v1 * wg[128 + lane];
    float r  = v0 * wa[lane]       + v1 * wa[32 + lane];
    #pragma unroll
    for (int o = 16; o; o >>= 1) {
        ps += __shfl_xor_sync(0xffffffffu, ps, o);
        pd += __shfl_xor_sync(0xffffffffu, pd, o);
        r  += __shfl_xor_sync(0xffffffffu, r,  o);
    }
    if (lane == 0) {
        g_ps[node] = ps;
        g_pd[node] = pd;
        g_sr[node] = make_float2(0.0f, r);
        g_cnt[node] = 0;
    }
}

// ---------------- K2: histogram ----------------
__global__ void k_hist(const int* __restrict__ dst) {
    int e = blockIdx.x * blockDim.x + threadIdx.x;
    if (e < N_EDGES) atomicAdd(&g_cnt[dst[e]], 1);
}

// ---------------- K3a: per-block scan ----------------
__global__ void k_scan1() {
    __shared__ int sh[SCAN_BLK];
    int tid = threadIdx.x;
    int i = blockIdx.x * SCAN_BLK + tid;
    int v = (i < N_NODES) ? g_cnt[i] : 0;
    sh[tid] = v;
    __syncthreads();
    #pragma unroll
    for (int off = 1; off < SCAN_BLK; off <<= 1) {
        int t = (tid >= off) ? sh[tid - off] : 0;
        __syncthreads();
        sh[tid] += t;
        __syncthreads();
    }
    if (i < N_NODES) g_off[i] = sh[tid] - v;
    if (tid == SCAN_BLK - 1) g_aux[blockIdx.x] = sh[tid];
}

// ---------------- K3b: redundant aux prefix + final offsets ----------------
__global__ void k_scan23() {
    __shared__ int s_aux[SCAN_NBLK];
    __shared__ int s_base;
    int tid = threadIdx.x;
    if (tid < SCAN_NBLK) s_aux[tid] = g_aux[tid];
    __syncthreads();
    if (tid == 0) {
        int run = 0;
        for (int b = 0; b < blockIdx.x; b++) run += s_aux[b];
        s_base = run;
    }
    __syncthreads();
    int i = blockIdx.x * SCAN_BLK + tid;
    if (i < N_NODES) {
        int o = g_off[i] + s_base;
        g_off[i] = o;
        g_cur[i] = o;
    }
    if (i == 0) g_off[N_NODES] = N_EDGES;
}

// ---------------- K4: scores + sorted CSR fill (8 lanes/edge) --------------
__global__ void k_fill(const float* __restrict__ ef,
                       const int* __restrict__ src,
                       const int* __restrict__ dst,
                       const float* __restrict__ wg,
                       const float* __restrict__ wa) {
    int gid = blockIdx.x * blockDim.x + threadIdx.x;
    int e = gid >> 3;
    int k = gid & 7;
    if (e >= N_EDGES) return;
    float4 v  = ((const float4*)ef)[(size_t)e * 8 + k];
    float4 w1 = ((const float4*)wg)[k];
    float4 w2 = ((const float4*)wa)[16 + k];
    float qe = v.x * w1.x + v.y * w1.y + v.z * w1.z + v.w * w1.w;
    float te = v.x * w2.x + v.y * w2.y + v.z * w2.z + v.w * w2.w;
    #pragma unroll
    for (int o = 4; o; o >>= 1) {
        qe += __shfl_xor_sync(0xffffffffu, qe, o);
        te += __shfl_xor_sync(0xffffffffu, te, o);
    }
    if (k == 0) {
        int s = src[e];
        int d = dst[e];
        float a  = qe + g_ps[s] + g_pd[d];
        float ee = __expf(a);              // scores O(1): max-free softmax
        atomicAdd(&g_sr[s].x, ee);
        int p = atomicAdd(&g_cur[d], 1);
        g_se [p] = make_int2(s, e);
        g_eet[p] = make_float2(ee, te);
    }
}

// ---------------- K5: fused edge-weights + gather + GEMV(relu) -------------
// Unnormalized accumulation: accum = (1/Σw) Σ w·x — scale once at the end.
__global__ void __launch_bounds__(256) k_gather_out(
        const float* __restrict__ h,
        const float* __restrict__ ef,
        const float* __restrict__ wlin,
        float* __restrict__ out) {
    extern __shared__ __align__(16) float smem[];
    float*  s_wT   = smem;                                  // [64][WROW]
    float*  s_hc   = smem + OUT_F * WROW;                   // [8][4][160]
    float4* s_meta = (float4*)(s_hc + 8 * 4 * IN_DIM);      // [8][32]

    int tid  = threadIdx.x;
    int warp = tid >> 5;
    int lane = tid & 31;

    for (int i = tid; i < IN_DIM * OUT_F; i += blockDim.x) {
        int k = i >> 6, c = i & 63;
        s_wT[c * WROW + k] = wlin[i];
    }
    __syncthreads();

    const unsigned long long* h64 = (const unsigned long long*)h;
    float*  hcW = s_hc + warp * (4 * IN_DIM);
    float4* mW  = s_meta + warp * 32;

    int gwarp  = blockIdx.x * 8 + warp;
    int nwarps = gridDim.x * 8;

    for (int g0 = gwarp * 4; g0 < N_NODES; g0 += nwarps * 4) {
        #pragma unroll
        for (int nn = 0; nn < 4; nn++) {
            int node = g0 + nn;
            if (node >= N_NODES) break;
            int beg = g_off[node];
            int end = g_off[node + 1];

            unsigned long long accH = 0;
            float accE = 0.0f;
            float se   = 0.0f;

            for (int base = beg; base < end; base += 32) {
                int i = base + lane;
                if (i < end) {
                    int2   sp  = g_se[i];            // contiguous
                    float2 eet = g_eet[i];           // contiguous
                    float2 sr  = g_sr[sp.x];         // random, L2-resident
                    float gamma = eet.x / sr.x;
                    float w = __expf(sr.y + gamma * eet.y);
                    se += w;
                    mW[lane] = make_float4(w, w * gamma,
                                           __int_as_float(sp.x),
                                           __int_as_float(sp.y));
                }
                __syncwarp();
                int cnt = min(32, end - base);
                #pragma unroll 8
                for (int j = 0; j < cnt; j++) {
                    float4 m = mW[j];                 // broadcast LDS.128
                    int s  = __float_as_int(m.z);
                    int ej = __float_as_int(m.w);
                    unsigned long long h2 = __ldg(&h64[(size_t)s * 32 + lane]);
                    float ev = __ldg(&ef[(size_t)ej * EDGE_DIM + lane]);
                    accH = fma2(pack2(m.x, m.x), h2, accH);
                    accE = fmaf(m.y, ev, accE);
                }
                __syncwarp();
            }

            #pragma unroll
            for (int o = 16; o; o >>= 1)
                se += __shfl_xor_sync(0xffffffffu, se, o);
            float inv = (end > beg) ? 1.0f / se : 0.0f;

            float2 own = ((const float2*)h)[(size_t)node * 32 + lane];
            float2 aH  = unpack2(accH);
            float* hc = hcW + nn * IN_DIM;
            ((float2*)hc)[lane]        = own;
            ((float2*)(hc + 64))[lane] = make_float2(aH.x * inv, aH.y * inv);
            hc[128 + lane]             = accE * inv;
        }
        __syncwarp();

        // ---- amortized 4-node GEMV with packed FFMA2 ----
        unsigned long long aA[4][2] = {};
        unsigned long long aB[4][2] = {};
        const ulonglong2* wA = (const ulonglong2*)&s_wT[lane * WROW];
        const ulonglong2* wB = (const ulonglong2*)&s_wT[(lane + 32) * WROW];
        const ulonglong2* hv0 = (const ulonglong2*)(hcW + 0 * IN_DIM);
        const ulonglong2* hv1 = (const ulonglong2*)(hcW + 1 * IN_DIM);
        const ulonglong2* hv2 = (const ulonglong2*)(hcW + 2 * IN_DIM);
        const ulonglong2* hv3 = (const ulonglong2*)(hcW + 3 * IN_DIM);

        #pragma unroll 4
        for (int q = 0; q < IN_DIM / 4; q++) {
            ulonglong2 va = wA[q];
            ulonglong2 vb = wB[q];
            ulonglong2 x0 = hv0[q], x1 = hv1[q], x2 = hv2[q], x3 = hv3[q];
            aA[0][0] = fma2(va.x, x0.x, aA[0][0]); aA[0][1] = fma2(va.y, x0.y, aA[0][1]);
            aA[1][0] = fma2(va.x, x1.x, aA[1][0]); aA[1][1] = fma2(va.y, x1.y, aA[1][1]);
            aA[2][0] = fma2(va.x, x2.x, aA[2][0]); aA[2][1] = fma2(va.y, x2.y, aA[2][1]);
            aA[3][0] = fma2(va.x, x3.x, aA[3][0]); aA[3][1] = fma2(va.y, x3.y, aA[3][1]);
            aB[0][0] = fma2(vb.x, x0.x, aB[0][0]); aB[0][1] = fma2(vb.y, x0.y, aB[0][1]);
            aB[1][0] = fma2(vb.x, x1.x, aB[1][0]); aB[1][1] = fma2(vb.y, x1.y, aB[1][1]);
            aB[2][0] = fma2(vb.x, x2.x, aB[2][0]); aB[2][1] = fma2(vb.y, x2.y, aB[2][1]);
            aB[3][0] = fma2(vb.x, x3.x, aB[3][0]); aB[3][1] = fma2(vb.y, x3.y, aB[3][1]);
        }

        #pragma unroll
        for (int nn = 0; nn < 4; nn++) {
            int node = g0 + nn;
            if (node >= N_NODES) break;
            float2 uA0 = unpack2(aA[nn][0]), uA1 = unpack2(aA[nn][1]);
            float2 uB0 = unpack2(aB[nn][0]), uB1 = unpack2(aB[nn][1]);
            float oA = (uA0.x + uA0.y) + (uA1.x + uA1.y);
            float oB = (uB0.x + uB0.y) + (uB1.x + uB1.y);
            out[(size_t)node * OUT_F + lane]      = fmaxf(oA, 0.f);
            out[(size_t)node * OUT_F + 32 + lane] = fmaxf(oB, 0.f);
        }
        __syncwarp();
    }
}

// ---------------- launcher ----------------
extern "C" void kernel_launch(void* const* d_in, const int* in_sizes, int n_in,
                              void* d_out, int out_size) {
    const float* h   = (const float*)d_in[0];
    const float* ef  = (const float*)d_in[1];
    const int*   src = (const int*)  d_in[2];
    const int*   dst = (const int*)  d_in[3];
    const float* wg  = (const float*)d_in[4];
    const float* wa  = (const float*)d_in[5];
    const float* wl  = (const float*)d_in[6];
    float* out = (float*)d_out;

    const int SMEM = (OUT_F * WROW + 8 * 4 * IN_DIM) * 4 + 8 * 32 * 16;  // ~66.5 KB
    cudaFuncSetAttribute(k_gather_out, cudaFuncAttributeMaxDynamicSharedMemorySize, SMEM);

    k_node_pre<<<(N_NODES + 7) / 8, 256>>>(h, wg, wa);
    k_hist<<<(N_EDGES + 255) / 256, 256>>>(dst);
    k_scan1<<<SCAN_NBLK, SCAN_BLK>>>();
    k_scan23<<<SCAN_NBLK, SCAN_BLK>>>();
    k_fill<<<((size_t)N_EDGES * 8 + 255) / 256, 256>>>(ef, src, dst, wg, wa);
    k_gather_out<<<592, 256, SMEM>>>(h, ef, wl, out);
}

// round 6
// speedup vs baseline: 1.2834x; 1.2317x over previous
#include <cuda_runtime.h>
#include <cuda_bf16.h>
#include <math_constants.h>

#define N_NODES 50000
#define N_EDGES 800000
#define NODE_DIM 64
#define EDGE_DIM 32
#define IN_DIM   160
#define OUT_F    64
#define WROW     164

#define SCAN_BLK 512
#define SCAN_NBLK ((N_NODES + SCAN_BLK - 1) / SCAN_BLK)   // 98

// ---------------- static scratch ----------------
__device__ float g_ps[N_NODES];
__device__ float g_pd[N_NODES];
__device__ float2 g_sr[N_NODES];        // (sum exp(a) per src, h.wa[0:64])
__device__ int   g_cnt[N_NODES];
__device__ int   g_off[N_NODES + 1];
__device__ int   g_cur[N_NODES];
__device__ int   g_aux[SCAN_NBLK];

__device__ int2   g_se [N_EDGES];       // (src, eid), dst-sorted
__device__ float2 g_eet[N_EDGES];       // (exp(a), e_ft.wa[64:96]), dst-sorted

// ---------------- packed f32x2 helpers ----------------
__device__ __forceinline__ unsigned long long fma2(unsigned long long a,
                                                   unsigned long long b,
                                                   unsigned long long c) {
    unsigned long long d;
    asm("fma.rn.f32x2 %0, %1, %2, %3;" : "=l"(d) : "l"(a), "l"(b), "l"(c));
    return d;
}
__device__ __forceinline__ unsigned long long pack2(float x, float y) {
    unsigned long long r;
    asm("mov.b64 %0, {%1, %2};" : "=l"(r) : "f"(x), "f"(y));
    return r;
}
__device__ __forceinline__ float2 unpack2(unsigned long long v) {
    float2 r;
    asm("mov.b64 {%0, %1}, %2;" : "=f"(r.x), "=f"(r.y) : "l"(v));
    return r;
}

// ---------------- K1: per-node dots + init ----------------
__global__ void k_node_pre(const float* __restrict__ h,
                           const float* __restrict__ wg,
                           const float* __restrict__ wa) {
    int node = blockIdx.x * (blockDim.x >> 5) + (threadIdx.x >> 5);
    int lane = threadIdx.x & 31;
    if (node >= N_NODES) return;
    const float* hp = h + (size_t)node * NODE_DIM;
    float v0 = hp[lane];
    float v1 = hp[lane + 32];
    float ps = v0 * wg[32 + lane]  + v1 * wg[64 + lane];
    float pd = v0 * wg[96 + lane]  + v1 * wg[128 + lane];
    float r  = v0 * wa[lane]       + v1 * wa[32 + lane];
    #pragma unroll
    for (int o = 16; o; o >>= 1) {
        ps += __shfl_xor_sync(0xffffffffu, ps, o);
        pd += __shfl_xor_sync(0xffffffffu, pd, o);
        r  += __shfl_xor_sync(0xffffffffu, r,  o);
    }
    if (lane == 0) {
        g_ps[node] = ps;
        g_pd[node] = pd;
        g_sr[node] = make_float2(0.0f, r);
        g_cnt[node] = 0;
    }
}

// ---------------- K2: histogram ----------------
__global__ void k_hist(const int* __restrict__ dst) {
    int e = blockIdx.x * blockDim.x + threadIdx.x;
    if (e < N_EDGES) atomicAdd(&g_cnt[dst[e]], 1);
}

// ---------------- K3a: per-block scan ----------------
__global__ void k_scan1() {
    __shared__ int sh[SCAN_BLK];
    int tid = threadIdx.x;
    int i = blockIdx.x * SCAN_BLK + tid;
    int v = (i < N_NODES) ? g_cnt[i] : 0;
    sh[tid] = v;
    __syncthreads();
    #pragma unroll
    for (int off = 1; off < SCAN_BLK; off <<= 1) {
        int t = (tid >= off) ? sh[tid - off] : 0;
        __syncthreads();
        sh[tid] += t;
        __syncthreads();
    }
    if (i < N_NODES) g_off[i] = sh[tid] - v;
    if (tid == SCAN_BLK - 1) g_aux[blockIdx.x] = sh[tid];
}

// ---------------- K3b: redundant aux prefix + final offsets ----------------
__global__ void k_scan23() {
    __shared__ int s_aux[SCAN_NBLK];
    __shared__ int s_base;
    int tid = threadIdx.x;
    if (tid < SCAN_NBLK) s_aux[tid] = g_aux[tid];
    __syncthreads();
    if (tid == 0) {
        int run = 0;
        for (int b = 0; b < blockIdx.x; b++) run += s_aux[b];
        s_base = run;
    }
    __syncthreads();
    int i = blockIdx.x * SCAN_BLK + tid;
    if (i < N_NODES) {
        int o = g_off[i] + s_base;
        g_off[i] = o;
        g_cur[i] = o;
    }
    if (i == 0) g_off[N_NODES] = N_EDGES;
}

// ---------------- K4: scores + sorted CSR fill (8 lanes/edge) --------------
__global__ void k_fill(const float* __restrict__ ef,
                       const int* __restrict__ src,
                       const int* __restrict__ dst,
                       const float* __restrict__ wg,
                       const float* __restrict__ wa) {
    int gid = blockIdx.x * blockDim.x + threadIdx.x;
    int e = gid >> 3;
    int k = gid & 7;
    if (e >= N_EDGES) return;
    float4 v  = ((const float4*)ef)[(size_t)e * 8 + k];
    float4 w1 = ((const float4*)wg)[k];
    float4 w2 = ((const float4*)wa)[16 + k];
    float qe = v.x * w1.x + v.y * w1.y + v.z * w1.z + v.w * w1.w;
    float te = v.x * w2.x + v.y * w2.y + v.z * w2.z + v.w * w2.w;
    #pragma unroll
    for (int o = 4; o; o >>= 1) {
        qe += __shfl_xor_sync(0xffffffffu, qe, o);
        te += __shfl_xor_sync(0xffffffffu, te, o);
    }
    if (k == 0) {
        int s = src[e];
        int d = dst[e];
        float a  = qe + g_ps[s] + g_pd[d];
        float ee = __expf(a);              // scores O(1): max-free softmax
        atomicAdd(&g_sr[s].x, ee);
        int p = atomicAdd(&g_cur[d], 1);
        g_se [p] = make_int2(s, e);
        g_eet[p] = make_float2(ee, te);
    }
}

// ---------------- K5: fused weights + 2-edge-parallel gather + GEMV --------
__global__ void __launch_bounds__(256) k_gather_out(
        const float* __restrict__ h,
        const float* __restrict__ ef,
        const float* __restrict__ wlin,
        float* __restrict__ out) {
    extern __shared__ __align__(16) float smem[];
    float*  s_wT   = smem;                                  // [64][WROW]
    float*  s_hc   = smem + OUT_F * WROW;                   // [8][4][160]
    float4* s_meta = (float4*)(s_hc + 8 * 4 * IN_DIM);      // [8][32]

    int tid  = threadIdx.x;
    int warp = tid >> 5;
    int lane = tid & 31;
    int grp  = lane >> 4;       // 0/1: which edges of the chunk
    int hl   = lane & 15;       // position within group

    for (int i = tid; i < IN_DIM * OUT_F; i += blockDim.x) {
        int k = i >> 6, c = i & 63;
        s_wT[c * WROW + k] = wlin[i];
    }
    __syncthreads();

    const ulonglong2*        h128 = (const ulonglong2*)h;           // 16 per row
    const unsigned long long* e64 = (const unsigned long long*)ef;  // 16 per row
    float*  hcW = s_hc + warp * (4 * IN_DIM);
    float4* mW  = s_meta + warp * 32;

    int gwarp  = blockIdx.x * 8 + warp;
    int nwarps = gridDim.x * 8;

    for (int g0 = gwarp * 4; g0 < N_NODES; g0 += nwarps * 4) {
        #pragma unroll
        for (int nn = 0; nn < 4; nn++) {
            int node = g0 + nn;
            if (node >= N_NODES) break;
            int beg = g_off[node];
            int end = g_off[node + 1];

            unsigned long long accHa = 0, accHb = 0;  // dims 4hl..4hl+3 (group partial)
            unsigned long long accE2 = 0;             // dims 2hl..2hl+1 (group partial)
            float se = 0.0f;

            for (int base = beg; base < end; base += 32) {
                int i = base + lane;
                if (i < end) {
                    int2   sp  = g_se[i];           // contiguous
                    float2 eet = g_eet[i];          // contiguous
                    float2 sr  = g_sr[sp.x];        // random, L2-resident
                    float gamma = eet.x / sr.x;
                    float w = __expf(sr.y + gamma * eet.y);
                    se += w;
                    mW[lane] = make_float4(w, w * gamma,
                                           __int_as_float(sp.x),
                                           __int_as_float(sp.y));
                }
                __syncwarp();
                int cnt  = min(32, end - base);
                int half = (cnt + 1) >> 1;
                #pragma unroll 4
                for (int t = 0; t < half; t++) {
                    int j = 2 * t + grp;
                    if (j < cnt) {
                        float4 m = mW[j];
                        int s  = __float_as_int(m.z);
                        int ej = __float_as_int(m.w);
                        ulonglong2 hv = __ldg(&h128[(size_t)s * 16 + hl]);   // LDG.128
                        unsigned long long ev = __ldg(&e64[(size_t)ej * 16 + hl]); // LDG.64
                        unsigned long long wpp = pack2(m.x, m.x);
                        accHa = fma2(wpp, hv.x, accHa);
                        accHb = fma2(wpp, hv.y, accHb);
                        accE2 = fma2(pack2(m.y, m.y), ev, accE2);
                    }
                }
                __syncwarp();
            }

            // reduce se over full warp
            #pragma unroll
            for (int o = 16; o; o >>= 1)
                se += __shfl_xor_sync(0xffffffffu, se, o);
            float inv = (end > beg) ? 1.0f / se : 0.0f;

            // combine the two 16-lane group partials
            float2 pa = unpack2(accHa), qa = unpack2(__shfl_xor_sync(0xffffffffu, accHa, 16));
            float2 pb = unpack2(accHb), qb = unpack2(__shfl_xor_sync(0xffffffffu, accHb, 16));
            float2 pe = unpack2(accE2), qe = unpack2(__shfl_xor_sync(0xffffffffu, accE2, 16));

            float* hc = hcW + nn * IN_DIM;
            float2 own = ((const float2*)h)[(size_t)node * 32 + lane];
            ((float2*)hc)[lane] = own;                                  // dims 0..63
            if (lane < 16) {
                ((float4*)(hc + 64))[hl] = make_float4((pa.x + qa.x) * inv,
                                                       (pa.y + qa.y) * inv,
                                                       (pb.x + qb.x) * inv,
                                                       (pb.y + qb.y) * inv); // 64..127
                ((float2*)(hc + 128))[hl] = make_float2((pe.x + qe.x) * inv,
                                                        (pe.y + qe.y) * inv); // 128..159
            }
        }
        __syncwarp();

        // ---- amortized 4-node GEMV with packed FFMA2 ----
        unsigned long long aA[4][2] = {};
        unsigned long long aB[4][2] = {};
        const ulonglong2* wA = (const ulonglong2*)&s_wT[lane * WROW];
        const ulonglong2* wB = (const ulonglong2*)&s_wT[(lane + 32) * WROW];
        const ulonglong2* hv0 = (const ulonglong2*)(hcW + 0 * IN_DIM);
        const ulonglong2* hv1 = (const ulonglong2*)(hcW + 1 * IN_DIM);
        const ulonglong2* hv2 = (const ulonglong2*)(hcW + 2 * IN_DIM);
        const ulonglong2* hv3 = (const ulonglong2*)(hcW + 3 * IN_DIM);

        #pragma unroll 4
        for (int q = 0; q < IN_DIM / 4; q++) {
            ulonglong2 va = wA[q];
            ulonglong2 vb = wB[q];
            ulonglong2 x0 = hv0[q], x1 = hv1[q], x2 = hv2[q], x3 = hv3[q];
            aA[0][0] = fma2(va.x, x0.x, aA[0][0]); aA[0][1] = fma2(va.y, x0.y, aA[0][1]);
            aA[1][0] = fma2(va.x, x1.x, aA[1][0]); aA[1][1] = fma2(va.y, x1.y, aA[1][1]);
            aA[2][0] = fma2(va.x, x2.x, aA[2][0]); aA[2][1] = fma2(va.y, x2.y, aA[2][1]);
            aA[3][0] = fma2(va.x, x3.x, aA[3][0]); aA[3][1] = fma2(va.y, x3.y, aA[3][1]);
            aB[0][0] = fma2(vb.x, x0.x, aB[0][0]); aB[0][1] = fma2(vb.y, x0.y, aB[0][1]);
            aB[1][0] = fma2(vb.x, x1.x, aB[1][0]); aB[1][1] = fma2(vb.y, x1.y, aB[1][1]);
            aB[2][0] = fma2(vb.x, x2.x, aB[2][0]); aB[2][1] = fma2(vb.y, x2.y, aB[2][1]);
            aB[3][0] = fma2(vb.x, x3.x, aB[3][0]); aB[3][1] = fma2(vb.y, x3.y, aB[3][1]);
        }

        #pragma unroll
        for (int nn = 0; nn < 4; nn++) {
            int node = g0 + nn;
            if (node >= N_NODES) break;
            float2 uA0 = unpack2(aA[nn][0]), uA1 = unpack2(aA[nn][1]);
            float2 uB0 = unpack2(aB[nn][0]), uB1 = unpack2(aB[nn][1]);
            float oA = (uA0.x + uA0.y) + (uA1.x + uA1.y);
            float oB = (uB0.x + uB0.y) + (uB1.x + uB1.y);
            out[(size_t)node * OUT_F + lane]      = fmaxf(oA, 0.f);
            out[(size_t)node * OUT_F + 32 + lane] = fmaxf(oB, 0.f);
        }
        __syncwarp();
    }
}

// ---------------- launcher ----------------
extern "C" void kernel_launch(void* const* d_in, const int* in_sizes, int n_in,
                              void* d_out, int out_size) {
    const float* h   = (const float*)d_in[0];
    const float* ef  = (const float*)d_in[1];
    const int*   src = (const int*)  d_in[2];
    const int*   dst = (const int*)  d_in[3];
    const float* wg  = (const float*)d_in[4];
    const float* wa  = (const float*)d_in[5];
    const float* wl  = (const float*)d_in[6];
    float* out = (float*)d_out;

    const int SMEM = (OUT_F * WROW + 8 * 4 * IN_DIM) * 4 + 8 * 32 * 16;  // ~66.5 KB
    cudaFuncSetAttribute(k_gather_out, cudaFuncAttributeMaxDynamicSharedMemorySize, SMEM);

    k_node_pre<<<(N_NODES + 7) / 8, 256>>>(h, wg, wa);
    k_hist<<<(N_EDGES + 255) / 256, 256>>>(dst);
    k_scan1<<<SCAN_NBLK, SCAN_BLK>>>();
    k_scan23<<<SCAN_NBLK, SCAN_BLK>>>();
    k_fill<<<((size_t)N_EDGES * 8 + 255) / 256, 256>>>(ef, src, dst, wg, wa);
    k_gather_out<<<444, 256, SMEM>>>(h, ef, wl, out);
}